// round 2
// baseline (speedup 1.0000x reference)
#include <cuda_runtime.h>
#include <math.h>

// Problem constants
#define NB   2
#define NS   1024
#define NHID 1024
#define NH   16
#define NP   2
#define ND   64
#define NBH  32          // NB*NH
#define NSV  2048        // NS*NP
#define NM   2048        // NB*NS
#define ATT_SCALE 0.125f // 1/sqrt(64)

// Scratch (no cudaMalloc allowed)
__device__ float g_proj[3][NM * NHID];        // q/k/v projections, (b*S+n, m*64+d)
__device__ float g_mix [3][NBH * NSV * ND];   // mixed q/k/v, (bh, v, d)
__device__ float g_attn[NBH * NSV * ND];      // SDPA output, (bh, v, d)
__device__ float g_ctx [NM * NHID];           // collapsed context, (b*S+n, h*64+d)

// ---------------------------------------------------------------------------
// SGEMM: C = A(2048x1024) @ Bw^T (Bw is N=1024 rows x K=1024, row-major).
// 128x128 block tile, BK=16, 256 threads, 8x8 microtile (split 4+4 halves).
// Global->register prefetch double-buffers the LDGs against the FFMA block.
// blockIdx.z selects one of 3 (B, C) pairs so the QKV projection is one launch.
// ---------------------------------------------------------------------------
__global__ __launch_bounds__(256, 2)
void sgemm3(const float* __restrict__ A,
            const float* __restrict__ B0, const float* __restrict__ B1,
            const float* __restrict__ B2,
            float* __restrict__ C0, float* __restrict__ C1, float* __restrict__ C2)
{
    const float* Bw = (blockIdx.z == 0) ? B0 : (blockIdx.z == 1) ? B1 : B2;
    float*       C  = (blockIdx.z == 0) ? C0 : (blockIdx.z == 1) ? C1 : C2;

    __shared__ float As[16][132];
    __shared__ float Bs[16][132];

    const int tid = threadIdx.x;
    const int tx  = tid & 15;
    const int ty  = tid >> 4;
    const int row0 = blockIdx.y * 128;
    const int col0 = blockIdx.x * 128;

    float acc[8][8];
#pragma unroll
    for (int i = 0; i < 8; i++)
#pragma unroll
        for (int j = 0; j < 8; j++) acc[i][j] = 0.f;

    float ra[8], rb[8];
    // prologue: prefetch first K-tile into registers
#pragma unroll
    for (int r = 0; r < 8; r++) {
        int idx = tid + r * 256;
        int mm = idx >> 4, kk = idx & 15;
        ra[r] = A [(size_t)(row0 + mm) * NHID + kk];
        rb[r] = Bw[(size_t)(col0 + mm) * NHID + kk];
    }

    for (int kb = 0; kb < NHID; kb += 16) {
        // commit prefetched tile to smem
#pragma unroll
        for (int r = 0; r < 8; r++) {
            int idx = tid + r * 256;
            int mm = idx >> 4, kk = idx & 15;
            As[kk][mm] = ra[r];
            Bs[kk][mm] = rb[r];
        }
        __syncthreads();

        // prefetch next K-tile (overlaps with the FFMA block below)
        if (kb + 16 < NHID) {
#pragma unroll
            for (int r = 0; r < 8; r++) {
                int idx = tid + r * 256;
                int mm = idx >> 4, kk = idx & 15;
                ra[r] = A [(size_t)(row0 + mm) * NHID + kb + 16 + kk];
                rb[r] = Bw[(size_t)(col0 + mm) * NHID + kb + 16 + kk];
            }
        }

#pragma unroll
        for (int k = 0; k < 16; k++) {
            float a[8], b[8];
            *(float4*)(a)     = *(const float4*)&As[k][ty * 4];
            *(float4*)(a + 4) = *(const float4*)&As[k][64 + ty * 4];
            *(float4*)(b)     = *(const float4*)&Bs[k][tx * 4];
            *(float4*)(b + 4) = *(const float4*)&Bs[k][64 + tx * 4];
#pragma unroll
            for (int i = 0; i < 8; i++)
#pragma unroll
                for (int j = 0; j < 8; j++) acc[i][j] += a[i] * b[j];
        }
        __syncthreads();
    }

#pragma unroll
    for (int i = 0; i < 8; i++) {
        int row = row0 + ((i < 4) ? (ty * 4 + i) : (64 + ty * 4 + i - 4));
        float4 v0 = make_float4(acc[i][0], acc[i][1], acc[i][2], acc[i][3]);
        float4 v1 = make_float4(acc[i][4], acc[i][5], acc[i][6], acc[i][7]);
        *(float4*)&C[(size_t)row * NHID + col0 + tx * 4]      = v0;
        *(float4*)&C[(size_t)row * NHID + col0 + 64 + tx * 4] = v1;
    }
}

// ---------------------------------------------------------------------------
// Head mixing: g_mix[t][(b*16+h)*2048 + n*2+p][d] =
//   sum_m alpha_t[m,h,p] * g_proj[t][(b*S+n), m*64+d]
// One block per (b,n); 256 threads.
// ---------------------------------------------------------------------------
__global__ __launch_bounds__(256)
void mix_kernel(const float* __restrict__ aq, const float* __restrict__ ak,
                const float* __restrict__ av)
{
    __shared__ float srow[3][1024];
    __shared__ float sal[3][512];

    const int tid = threadIdx.x;
    const int bn  = blockIdx.x;        // b*1024 + n
    const int b   = bn >> 10;
    const int n   = bn & 1023;

#pragma unroll
    for (int t = 0; t < 3; t++)
#pragma unroll
        for (int r = 0; r < 4; r++)
            srow[t][tid + r * 256] = g_proj[t][(size_t)bn * NHID + tid + r * 256];

    const float* al[3] = { aq, ak, av };
#pragma unroll
    for (int t = 0; t < 3; t++) {
        sal[t][tid]       = al[t][tid];
        sal[t][tid + 256] = al[t][tid + 256];
    }
    __syncthreads();

    const int d   = tid & 63;
    const int hp0 = tid >> 6;          // 0..3

#pragma unroll
    for (int t = 0; t < 3; t++) {
#pragma unroll
        for (int r = 0; r < 8; r++) {
            int hp = hp0 + r * 4;
            int h = hp >> 1, p = hp & 1;
            float s = 0.f;
#pragma unroll
            for (int m = 0; m < 16; m++)
                s += sal[t][(m * 16 + h) * 2 + p] * srow[t][m * 64 + d];
            g_mix[t][((size_t)(b * 16 + h) * NSV + (n * 2 + p)) * ND + d] = s;
        }
    }
}

// ---------------------------------------------------------------------------
// Flash attention (fp32, causal, D=64). BQ=BK=64, 256 threads, 4x4 microtile.
// grid = (32 q-tiles, 32 batch-heads). Heaviest q-tiles launched first.
// ---------------------------------------------------------------------------
__global__ __launch_bounds__(256, 2)
void flash_kernel(const float* __restrict__ Qm, const float* __restrict__ Km,
                  const float* __restrict__ Vm, float* __restrict__ O)
{
    extern __shared__ float sm[];
    float* Qs = sm;                 // [64][68] transposed: Qs[d*68+m]
    float* Ks = sm + 4352;          // [64][68] transposed: Ks[d*68+c]
    float* Vs = sm + 8704;          // [64][68] natural:    Vs[c*68+d]
    float* Ps = sm + 13056;         // [64][68] transposed: Ps[c*68+m]

    const int tid = threadIdx.x;
    const int tx  = tid & 15;
    const int ty  = tid >> 4;
    const int qt  = gridDim.x - 1 - blockIdx.x;   // heavy tiles first
    const int bh  = blockIdx.y;

    const float* Qg = Qm + ((size_t)bh * NSV + qt * 64) * ND;
#pragma unroll
    for (int r = 0; r < 16; r++) {
        int idx = tid + r * 256;
        int m = idx >> 6, d = idx & 63;
        Qs[d * 68 + m] = Qg[idx];
    }

    float mrow[4], lrow[4], o[4][4];
#pragma unroll
    for (int i = 0; i < 4; i++) {
        mrow[i] = -1e30f; lrow[i] = 0.f;
#pragma unroll
        for (int j = 0; j < 4; j++) o[i][j] = 0.f;
    }

    for (int kt = 0; kt <= qt; kt++) {
        const float* Kg = Km + ((size_t)bh * NSV + kt * 64) * ND;
        const float* Vg = Vm + ((size_t)bh * NSV + kt * 64) * ND;

        __syncthreads();   // previous PV reads of Vs/Ps done (also covers Qs fill)
#pragma unroll
        for (int r = 0; r < 16; r++) {
            int idx = tid + r * 256;
            int c = idx >> 6, d = idx & 63;
            Ks[d * 68 + c] = Kg[idx];
            Vs[c * 68 + d] = Vg[idx];
        }
        __syncthreads();

        // S = Q @ K^T (tile)
        float s[4][4];
#pragma unroll
        for (int i = 0; i < 4; i++)
#pragma unroll
            for (int j = 0; j < 4; j++) s[i][j] = 0.f;

#pragma unroll 16
        for (int d = 0; d < 64; d++) {
            float q4[4], k4[4];
            *(float4*)q4 = *(const float4*)&Qs[d * 68 + ty * 4];
            *(float4*)k4 = *(const float4*)&Ks[d * 68 + tx * 4];
#pragma unroll
            for (int i = 0; i < 4; i++)
#pragma unroll
                for (int j = 0; j < 4; j++) s[i][j] += q4[i] * k4[j];
        }

        // scale + causal mask on virtual positions
        const int vqb = qt * 64 + ty * 4;
        const int vkb = kt * 64 + tx * 4;
#pragma unroll
        for (int i = 0; i < 4; i++)
#pragma unroll
            for (int j = 0; j < 4; j++)
                s[i][j] = (vkb + j <= vqb + i) ? s[i][j] * ATT_SCALE : -1e30f;

        // online softmax (row state replicated across the 16 tx lanes)
#pragma unroll
        for (int i = 0; i < 4; i++) {
            float mx = fmaxf(fmaxf(s[i][0], s[i][1]), fmaxf(s[i][2], s[i][3]));
#pragma unroll
            for (int off = 1; off < 16; off <<= 1)
                mx = fmaxf(mx, __shfl_xor_sync(0xffffffffu, mx, off));
            float mnew = fmaxf(mrow[i], mx);
            float corr = __expf(mrow[i] - mnew);
            float sum = 0.f;
#pragma unroll
            for (int j = 0; j < 4; j++) {
                s[i][j] = __expf(s[i][j] - mnew);
                sum += s[i][j];
            }
#pragma unroll
            for (int off = 1; off < 16; off <<= 1)
                sum += __shfl_xor_sync(0xffffffffu, sum, off);
            lrow[i] = lrow[i] * corr + sum;
            mrow[i] = mnew;
#pragma unroll
            for (int j = 0; j < 4; j++) o[i][j] *= corr;
        }

        // stage P transposed for the PV GEMM
#pragma unroll
        for (int j = 0; j < 4; j++) {
            float4 pv = make_float4(s[0][j], s[1][j], s[2][j], s[3][j]);
            *(float4*)&Ps[(tx * 4 + j) * 68 + ty * 4] = pv;
        }
        __syncthreads();

        // O += P @ V
#pragma unroll 16
        for (int c = 0; c < 64; c++) {
            float p4[4], v4[4];
            *(float4*)p4 = *(const float4*)&Ps[c * 68 + ty * 4];
            *(float4*)v4 = *(const float4*)&Vs[c * 68 + tx * 4];
#pragma unroll
            for (int i = 0; i < 4; i++)
#pragma unroll
                for (int j = 0; j < 4; j++) o[i][j] += p4[i] * v4[j];
        }
    }

#pragma unroll
    for (int i = 0; i < 4; i++) {
        float inv = 1.0f / lrow[i];
        float4 ov = make_float4(o[i][0] * inv, o[i][1] * inv,
                                o[i][2] * inv, o[i][3] * inv);
        *(float4*)&O[((size_t)bh * NSV + qt * 64 + ty * 4 + i) * ND + tx * 4] = ov;
    }
}

// ---------------------------------------------------------------------------
// Collapse pseudo-heads: g_ctx[b*S+n][h*64+d] =
//   sum_{o=m*2+p} collapse[h,o] * g_attn[(b*16+m)][n*2+p][d]
// ---------------------------------------------------------------------------
__global__ __launch_bounds__(256)
void collapse_kernel(const float* __restrict__ cw)
{
    __shared__ float sa[2048];   // [o=m*2+p][d]
    __shared__ float sc[512];    // [h][o]

    const int tid = threadIdx.x;
    const int bn  = blockIdx.x;
    const int b   = bn >> 10;
    const int n   = bn & 1023;

#pragma unroll
    for (int r = 0; r < 8; r++) {
        int idx = tid + r * 256;
        int mp = idx >> 6, d = idx & 63;
        int m = mp >> 1, p = mp & 1;
        sa[idx] = g_attn[((size_t)(b * 16 + m) * NSV + (n * 2 + p)) * ND + d];
    }
    sc[tid]       = cw[tid];
    sc[tid + 256] = cw[tid + 256];
    __syncthreads();

    const int d  = tid & 63;
    const int h0 = tid >> 6;
#pragma unroll
    for (int r = 0; r < 4; r++) {
        int h = h0 + r * 4;
        float s = 0.f;
#pragma unroll
        for (int o = 0; o < 32; o++)
            s += sc[h * 32 + o] * sa[o * 64 + d];
        g_ctx[(size_t)bn * NHID + h * 64 + d] = s;
    }
}

// ---------------------------------------------------------------------------
extern "C" void kernel_launch(void* const* d_in, const int* in_sizes, int n_in,
                              void* d_out, int out_size)
{
    const float* x  = (const float*)d_in[0];
    const float* Wq = (const float*)d_in[1];
    const float* Wk = (const float*)d_in[2];
    const float* Wv = (const float*)d_in[3];
    const float* Wo = (const float*)d_in[4];
    const float* aq = (const float*)d_in[5];
    const float* ak = (const float*)d_in[6];
    const float* av = (const float*)d_in[7];
    const float* cw = (const float*)d_in[8];
    float* out = (float*)d_out;

    float *pProj, *pMix, *pAttn, *pCtx;
    cudaGetSymbolAddress((void**)&pProj, g_proj);
    cudaGetSymbolAddress((void**)&pMix,  g_mix);
    cudaGetSymbolAddress((void**)&pAttn, g_attn);
    cudaGetSymbolAddress((void**)&pCtx,  g_ctx);

    // 1) QKV projection (single launch, z selects q/k/v)
    dim3 gProj(NHID / 128, NM / 128, 3);
    sgemm3<<<gProj, 256>>>(x, Wq, Wk, Wv,
                           pProj,
                           pProj + (size_t)NM * NHID,
                           pProj + 2 * (size_t)NM * NHID);

    // 2) head mixing
    mix_kernel<<<NM, 256>>>(aq, ak, av);

    // 3) causal flash attention over virtual positions
    const int smemBytes = 4 * 64 * 68 * (int)sizeof(float);   // 69632
    cudaFuncSetAttribute(flash_kernel,
                         cudaFuncAttributeMaxDynamicSharedMemorySize, smemBytes);
    dim3 gF(NSV / 64, NBH, 1);
    flash_kernel<<<gF, 256, smemBytes>>>(pMix,
                                         pMix + (size_t)NBH * NSV * ND,
                                         pMix + 2 * (size_t)NBH * NSV * ND,
                                         pAttn);

    // 4) collapse pseudo-heads
    collapse_kernel<<<NM, 256>>>(cw);

    // 5) output projection
    dim3 gOut(NHID / 128, NM / 128, 1);
    sgemm3<<<gOut, 256>>>(pCtx, Wo, Wo, Wo, out, out, out);
}

// round 9
// speedup vs baseline: 2.1620x; 2.1620x over previous
#include <cuda_runtime.h>
#include <cuda_bf16.h>
#include <math.h>
#include <cstdint>

// Problem constants
#define NB   2
#define NS   1024
#define NHID 1024
#define NH   16
#define NP   2
#define ND   64
#define NBH  32          // NB*NH
#define NSV  2048        // NS*NP
#define NM   2048        // NB*NS
#define ATT_SCALE 0.125f // 1/sqrt(64)

// Scratch (no cudaMalloc allowed)
__device__ float g_proj[3][NM * NHID];        // q/k/v projections, (b*S+n, m*64+d)
__device__ float g_mix [3][NBH * NSV * ND];   // mixed q/k/v, (bh, v, d)
__device__ float g_attn[NBH * NSV * ND];      // SDPA output, (bh, v, d)
__device__ float g_ctx [NM * NHID];           // collapsed context, (b*S+n, h*64+d)

// bf16 warp MMA: D = A(16x16,row) @ B(16x8,col) + D, fp32 accum.
__device__ __forceinline__ void mma16816(float* c, const uint32_t* a, const uint32_t* b) {
    asm volatile(
        "mma.sync.aligned.m16n8k16.row.col.f32.bf16.bf16.f32 "
        "{%0,%1,%2,%3}, {%4,%5,%6,%7}, {%8,%9}, {%0,%1,%2,%3};"
        : "+f"(c[0]), "+f"(c[1]), "+f"(c[2]), "+f"(c[3])
        : "r"(a[0]), "r"(a[1]), "r"(a[2]), "r"(a[3]), "r"(b[0]), "r"(b[1]));
}

__device__ __forceinline__ uint32_t pack_hi2(float x, float y) {
    __nv_bfloat162 t(__float2bfloat16(x), __float2bfloat16(y));
    return *reinterpret_cast<uint32_t*>(&t);
}
__device__ __forceinline__ uint32_t pack_lo2(float x, float y) {
    __nv_bfloat16 hx = __float2bfloat16(x), hy = __float2bfloat16(y);
    __nv_bfloat162 t(__float2bfloat16(x - __bfloat162float(hx)),
                     __float2bfloat16(y - __bfloat162float(hy)));
    return *reinterpret_cast<uint32_t*>(&t);
}

// ---------------------------------------------------------------------------
// bf16x3 split-precision tensor-core GEMM (warp mma.sync path):
// C(2048x1024) = A(2048x1024) @ Bw^T, Bw row-major (N rows x K), fp32 in/out.
// 128x128 CTA tile, 8 warps (32x64 each), BK=32 chunks, smem stride 40.
// blockIdx.z selects (Bw, C) so QKV is a single launch.
// ---------------------------------------------------------------------------
#define BK      32
#define ASTR    40   // bf16 elements per smem row (conflict-free residues)

__global__ __launch_bounds__(256, 2)
void gemm3_mma(const float* __restrict__ A,
               const float* __restrict__ B0, const float* __restrict__ B1,
               const float* __restrict__ B2,
               float* __restrict__ C0, float* __restrict__ C1, float* __restrict__ C2)
{
    const float* Bw = (blockIdx.z == 0) ? B0 : (blockIdx.z == 1) ? B1 : B2;
    float*       C  = (blockIdx.z == 0) ? C0 : (blockIdx.z == 1) ? C1 : C2;

    __shared__ __align__(16) __nv_bfloat16 sAh[128 * ASTR];
    __shared__ __align__(16) __nv_bfloat16 sAl[128 * ASTR];
    __shared__ __align__(16) __nv_bfloat16 sBh[128 * ASTR];
    __shared__ __align__(16) __nv_bfloat16 sBl[128 * ASTR];

    const int tid  = threadIdx.x;
    const int wid  = tid >> 5;
    const int lane = tid & 31;
    const int wm   = wid & 3;          // warp row (0..3) -> rows wm*32
    const int wn   = wid >> 2;         // warp col (0..1) -> cols wn*64
    const int row0 = blockIdx.y * 128;
    const int col0 = blockIdx.x * 128;

    const int fr = lane >> 2;          // 0..7
    const int cp = lane & 3;           // 0..3

    float acc[2][8][4];
#pragma unroll
    for (int mi = 0; mi < 2; mi++)
#pragma unroll
        for (int ni = 0; ni < 8; ni++)
#pragma unroll
            for (int j = 0; j < 4; j++) acc[mi][ni][j] = 0.f;

    for (int kb = 0; kb < NHID; kb += BK) {
        __syncthreads();   // previous chunk's fragment reads done
#pragma unroll
        for (int i = 0; i < 4; i++) {
            int idx = tid + i * 256;          // 0..1023 float4 slots
            int row = idx >> 3;               // 0..127
            int jc  = (idx & 7) * 4;          // col 0..28

            float4 va = *(const float4*)&A[(size_t)(row0 + row) * NHID + kb + jc];
            *(uint2*)&sAh[row * ASTR + jc] =
                make_uint2(pack_hi2(va.x, va.y), pack_hi2(va.z, va.w));
            *(uint2*)&sAl[row * ASTR + jc] =
                make_uint2(pack_lo2(va.x, va.y), pack_lo2(va.z, va.w));

            float4 vb = *(const float4*)&Bw[(size_t)(col0 + row) * NHID + kb + jc];
            *(uint2*)&sBh[row * ASTR + jc] =
                make_uint2(pack_hi2(vb.x, vb.y), pack_hi2(vb.z, vb.w));
            *(uint2*)&sBl[row * ASTR + jc] =
                make_uint2(pack_lo2(vb.x, vb.y), pack_lo2(vb.z, vb.w));
        }
        __syncthreads();

#pragma unroll
        for (int ks = 0; ks < 2; ks++) {
            const int k0 = ks * 16;
            uint32_t ah[2][4], al[2][4];
#pragma unroll
            for (int mi = 0; mi < 2; mi++) {
                int rb = wm * 32 + mi * 16;
                const __nv_bfloat16* p0 = &sAh[(rb + fr) * ASTR + k0 + cp * 2];
                const __nv_bfloat16* p1 = &sAh[(rb + fr + 8) * ASTR + k0 + cp * 2];
                ah[mi][0] = *(const uint32_t*)p0;
                ah[mi][1] = *(const uint32_t*)p1;
                ah[mi][2] = *(const uint32_t*)(p0 + 8);
                ah[mi][3] = *(const uint32_t*)(p1 + 8);
                const __nv_bfloat16* q0 = &sAl[(rb + fr) * ASTR + k0 + cp * 2];
                const __nv_bfloat16* q1 = &sAl[(rb + fr + 8) * ASTR + k0 + cp * 2];
                al[mi][0] = *(const uint32_t*)q0;
                al[mi][1] = *(const uint32_t*)q1;
                al[mi][2] = *(const uint32_t*)(q0 + 8);
                al[mi][3] = *(const uint32_t*)(q1 + 8);
            }
#pragma unroll
            for (int ni = 0; ni < 8; ni++) {
                int nb = wn * 64 + ni * 8;
                const __nv_bfloat16* pb = &sBh[(nb + fr) * ASTR + k0 + cp * 2];
                const __nv_bfloat16* ql = &sBl[(nb + fr) * ASTR + k0 + cp * 2];
                uint32_t bh[2] = { *(const uint32_t*)pb, *(const uint32_t*)(pb + 8) };
                uint32_t bl[2] = { *(const uint32_t*)ql, *(const uint32_t*)(ql + 8) };
#pragma unroll
                for (int mi = 0; mi < 2; mi++) {
                    mma16816(acc[mi][ni], ah[mi], bh);   // hi*hi
                    mma16816(acc[mi][ni], ah[mi], bl);   // hi*lo
                    mma16816(acc[mi][ni], al[mi], bh);   // lo*hi
                }
            }
        }
    }

#pragma unroll
    for (int mi = 0; mi < 2; mi++) {
#pragma unroll
        for (int ni = 0; ni < 8; ni++) {
            int row = row0 + wm * 32 + mi * 16 + fr;
            int col = col0 + wn * 64 + ni * 8 + cp * 2;
            *(float2*)&C[(size_t)row * NHID + col] =
                make_float2(acc[mi][ni][0], acc[mi][ni][1]);
            *(float2*)&C[(size_t)(row + 8) * NHID + col] =
                make_float2(acc[mi][ni][2], acc[mi][ni][3]);
        }
    }
}

// ---------------------------------------------------------------------------
// Head mixing
// ---------------------------------------------------------------------------
__global__ __launch_bounds__(256)
void mix_kernel(const float* __restrict__ aq, const float* __restrict__ ak,
                const float* __restrict__ av)
{
    __shared__ float srow[3][1024];
    __shared__ float sal[3][512];

    const int tid = threadIdx.x;
    const int bn  = blockIdx.x;
    const int b   = bn >> 10;
    const int n   = bn & 1023;

#pragma unroll
    for (int t = 0; t < 3; t++)
#pragma unroll
        for (int r = 0; r < 4; r++)
            srow[t][tid + r * 256] = g_proj[t][(size_t)bn * NHID + tid + r * 256];

    const float* al[3] = { aq, ak, av };
#pragma unroll
    for (int t = 0; t < 3; t++) {
        sal[t][tid]       = al[t][tid];
        sal[t][tid + 256] = al[t][tid + 256];
    }
    __syncthreads();

    const int d   = tid & 63;
    const int hp0 = tid >> 6;

#pragma unroll
    for (int t = 0; t < 3; t++) {
#pragma unroll
        for (int r = 0; r < 8; r++) {
            int hp = hp0 + r * 4;
            int h = hp >> 1, p = hp & 1;
            float s = 0.f;
#pragma unroll
            for (int m = 0; m < 16; m++)
                s += sal[t][(m * 16 + h) * 2 + p] * srow[t][m * 64 + d];
            g_mix[t][((size_t)(b * 16 + h) * NSV + (n * 2 + p)) * ND + d] = s;
        }
    }
}

// ---------------------------------------------------------------------------
// Flash attention on tensor cores, bf16x3 split precision (causal, D=64).
// BQ=128 (8 warps x m16), BK=64. grid = (16 q-tiles, 32 bh), heavy-first.
// smem stride 72 => fragment banks 4*fr+cp (conflict-free).
// V stored transposed with kpos ^= ((d>>2)&7)<<3 swizzle.
// ---------------------------------------------------------------------------
#define FSTR 72

__global__ __launch_bounds__(256, 1)
void flash_mma(const float* __restrict__ Qm, const float* __restrict__ Km,
               const float* __restrict__ Vm, float* __restrict__ O)
{
    extern __shared__ __nv_bfloat16 fsm[];
    __nv_bfloat16* Qh = fsm;                    // [128][72]
    __nv_bfloat16* Ql = Qh + 128 * FSTR;
    __nv_bfloat16* Kh = Ql + 128 * FSTR;        // [64][72] (row=kpos, col=d)
    __nv_bfloat16* Kl = Kh + 64 * FSTR;
    __nv_bfloat16* Vh = Kl + 64 * FSTR;         // [64][72] (row=d, col=kpos^swz)
    __nv_bfloat16* Vl = Vh + 64 * FSTR;

    const int tid  = threadIdx.x;
    const int wid  = tid >> 5;
    const int lane = tid & 31;
    const int fr   = lane >> 2;
    const int cp   = lane & 3;
    const int qt   = 15 - blockIdx.x;           // heavy tiles first
    const int bh   = blockIdx.y;

    // load Q tile (128 x 64) -> hi/lo split
    const float* Qg = Qm + ((size_t)bh * NSV + qt * 128) * ND;
#pragma unroll
    for (int i = 0; i < 8; i++) {
        int idx = tid + i * 256;                // 0..2047 float4 slots
        int row = idx >> 4;
        int jc  = (idx & 15) * 4;
        float4 v = *(const float4*)&Qg[row * ND + jc];
        *(uint2*)&Qh[row * FSTR + jc] = make_uint2(pack_hi2(v.x, v.y), pack_hi2(v.z, v.w));
        *(uint2*)&Ql[row * FSTR + jc] = make_uint2(pack_lo2(v.x, v.y), pack_lo2(v.z, v.w));
    }

    float m0 = -1e30f, m1 = -1e30f, l0 = 0.f, l1 = 0.f;
    float o[8][4];
#pragma unroll
    for (int nf = 0; nf < 8; nf++)
#pragma unroll
        for (int j = 0; j < 4; j++) o[nf][j] = 0.f;

    const int rowg0 = qt * 128 + wid * 16 + fr;     // global virtual row (this thread)
    const int rowg1 = rowg0 + 8;
    const int kts = 2 * qt + 2;

    for (int kt = 0; kt < kts; kt++) {
        const float* Kg = Km + ((size_t)bh * NSV + kt * 64) * ND;
        const float* Vg = Vm + ((size_t)bh * NSV + kt * 64) * ND;

        __syncthreads();   // prev iter fragment reads done (covers Q fill too)
#pragma unroll
        for (int i = 0; i < 4; i++) {
            int idx = tid + i * 256;            // 0..1023 float4 slots
            int row = idx >> 4;                 // kpos 0..63
            int jc  = (idx & 15) * 4;           // d 0..60
            float4 kv = *(const float4*)&Kg[row * ND + jc];
            *(uint2*)&Kh[row * FSTR + jc] = make_uint2(pack_hi2(kv.x, kv.y), pack_hi2(kv.z, kv.w));
            *(uint2*)&Kl[row * FSTR + jc] = make_uint2(pack_lo2(kv.x, kv.y), pack_lo2(kv.z, kv.w));

            float4 vv = *(const float4*)&Vg[row * ND + jc];
            float ve[4] = { vv.x, vv.y, vv.z, vv.w };
#pragma unroll
            for (int e = 0; e < 4; e++) {
                int d  = jc + e;
                int kx = row ^ (((d >> 2) & 7) << 3);
                __nv_bfloat16 hv = __float2bfloat16(ve[e]);
                Vh[d * FSTR + kx] = hv;
                Vl[d * FSTR + kx] = __float2bfloat16(ve[e] - __bfloat162float(hv));
            }
        }
        __syncthreads();

        // ---- S = Q @ K^T (128x64 tile; this warp: rows wid*16..+16) ----
        float s[8][4];
#pragma unroll
        for (int nf = 0; nf < 8; nf++)
#pragma unroll
            for (int j = 0; j < 4; j++) s[nf][j] = 0.f;

#pragma unroll
        for (int ds = 0; ds < 4; ds++) {
            const int k0 = ds * 16;
            const int rb = wid * 16;
            const __nv_bfloat16* p0 = &Qh[(rb + fr) * FSTR + k0 + cp * 2];
            const __nv_bfloat16* p1 = &Qh[(rb + fr + 8) * FSTR + k0 + cp * 2];
            uint32_t ah[4] = { *(const uint32_t*)p0, *(const uint32_t*)p1,
                               *(const uint32_t*)(p0 + 8), *(const uint32_t*)(p1 + 8) };
            const __nv_bfloat16* q0 = &Ql[(rb + fr) * FSTR + k0 + cp * 2];
            const __nv_bfloat16* q1 = &Ql[(rb + fr + 8) * FSTR + k0 + cp * 2];
            uint32_t al[4] = { *(const uint32_t*)q0, *(const uint32_t*)q1,
                               *(const uint32_t*)(q0 + 8), *(const uint32_t*)(q1 + 8) };
#pragma unroll
            for (int nf = 0; nf < 8; nf++) {
                int nb = nf * 8;
                const __nv_bfloat16* pb = &Kh[(nb + fr) * FSTR + k0 + cp * 2];
                const __nv_bfloat16* ql = &Kl[(nb + fr) * FSTR + k0 + cp * 2];
                uint32_t bh[2] = { *(const uint32_t*)pb, *(const uint32_t*)(pb + 8) };
                uint32_t bl[2] = { *(const uint32_t*)ql, *(const uint32_t*)(ql + 8) };
                mma16816(s[nf], ah, bh);
                mma16816(s[nf], ah, bl);
                mma16816(s[nf], al, bh);
            }
        }

        // ---- scale + causal mask ----
#pragma unroll
        for (int nf = 0; nf < 8; nf++) {
            int c0 = kt * 64 + nf * 8 + cp * 2;
            s[nf][0] = (c0     <= rowg0) ? s[nf][0] * ATT_SCALE : -1e30f;
            s[nf][1] = (c0 + 1 <= rowg0) ? s[nf][1] * ATT_SCALE : -1e30f;
            s[nf][2] = (c0     <= rowg1) ? s[nf][2] * ATT_SCALE : -1e30f;
            s[nf][3] = (c0 + 1 <= rowg1) ? s[nf][3] * ATT_SCALE : -1e30f;
        }

        // ---- online softmax (rows fr, fr+8; reduce over quad lanes) ----
        float mx0 = -1e30f, mx1 = -1e30f;
#pragma unroll
        for (int nf = 0; nf < 8; nf++) {
            mx0 = fmaxf(mx0, fmaxf(s[nf][0], s[nf][1]));
            mx1 = fmaxf(mx1, fmaxf(s[nf][2], s[nf][3]));
        }
#pragma unroll
        for (int off = 1; off < 4; off <<= 1) {
            mx0 = fmaxf(mx0, __shfl_xor_sync(0xffffffffu, mx0, off));
            mx1 = fmaxf(mx1, __shfl_xor_sync(0xffffffffu, mx1, off));
        }
        float mn0 = fmaxf(m0, mx0), mn1 = fmaxf(m1, mx1);
        float cr0 = __expf(m0 - mn0), cr1 = __expf(m1 - mn1);
        float sm0 = 0.f, sm1 = 0.f;
#pragma unroll
        for (int nf = 0; nf < 8; nf++) {
            s[nf][0] = __expf(s[nf][0] - mn0);
            s[nf][1] = __expf(s[nf][1] - mn0);
            s[nf][2] = __expf(s[nf][2] - mn1);
            s[nf][3] = __expf(s[nf][3] - mn1);
            sm0 += s[nf][0] + s[nf][1];
            sm1 += s[nf][2] + s[nf][3];
        }
#pragma unroll
        for (int off = 1; off < 4; off <<= 1) {
            sm0 += __shfl_xor_sync(0xffffffffu, sm0, off);
            sm1 += __shfl_xor_sync(0xffffffffu, sm1, off);
        }
        l0 = l0 * cr0 + sm0;  m0 = mn0;
        l1 = l1 * cr1 + sm1;  m1 = mn1;
#pragma unroll
        for (int nf = 0; nf < 8; nf++) {
            o[nf][0] *= cr0; o[nf][1] *= cr0;
            o[nf][2] *= cr1; o[nf][3] *= cr1;
        }

        // ---- O += P @ V (P converted reg->reg to A-frags, split) ----
#pragma unroll
        for (int ks = 0; ks < 4; ks++) {
            const int k0 = ks * 16;
            uint32_t ph[4], pl[4];
            ph[0] = pack_hi2(s[2*ks][0],   s[2*ks][1]);
            ph[1] = pack_hi2(s[2*ks][2],   s[2*ks][3]);
            ph[2] = pack_hi2(s[2*ks+1][0], s[2*ks+1][1]);
            ph[3] = pack_hi2(s[2*ks+1][2], s[2*ks+1][3]);
            pl[0] = pack_lo2(s[2*ks][0],   s[2*ks][1]);
            pl[1] = pack_lo2(s[2*ks][2],   s[2*ks][3]);
            pl[2] = pack_lo2(s[2*ks+1][0], s[2*ks+1][1]);
            pl[3] = pack_lo2(s[2*ks+1][2], s[2*ks+1][3]);
#pragma unroll
            for (int nf = 0; nf < 8; nf++) {
                int d  = nf * 8 + fr;
                int sw = ((d >> 2) & 7) << 3;
                int kx0 = (k0 + cp * 2) ^ sw;
                int kx1 = (k0 + cp * 2 + 8) ^ sw;
                uint32_t bh[2] = { *(const uint32_t*)&Vh[d * FSTR + kx0],
                                   *(const uint32_t*)&Vh[d * FSTR + kx1] };
                uint32_t bl[2] = { *(const uint32_t*)&Vl[d * FSTR + kx0],
                                   *(const uint32_t*)&Vl[d * FSTR + kx1] };
                mma16816(o[nf], ph, bh);
                mma16816(o[nf], ph, bl);
                mma16816(o[nf], pl, bh);
            }
        }
    }

    // ---- normalize + store ----
    float i0 = 1.0f / l0, i1 = 1.0f / l1;
    float* Op = O + ((size_t)bh * NSV) * ND;
#pragma unroll
    for (int nf = 0; nf < 8; nf++) {
        int col = nf * 8 + cp * 2;
        *(float2*)&Op[(size_t)rowg0 * ND + col] = make_float2(o[nf][0] * i0, o[nf][1] * i0);
        *(float2*)&Op[(size_t)rowg1 * ND + col] = make_float2(o[nf][2] * i1, o[nf][3] * i1);
    }
}

// ---------------------------------------------------------------------------
// Collapse pseudo-heads
// ---------------------------------------------------------------------------
__global__ __launch_bounds__(256)
void collapse_kernel(const float* __restrict__ cw)
{
    __shared__ float sa[2048];
    __shared__ float sc[512];

    const int tid = threadIdx.x;
    const int bn  = blockIdx.x;
    const int b   = bn >> 10;
    const int n   = bn & 1023;

#pragma unroll
    for (int r = 0; r < 8; r++) {
        int idx = tid + r * 256;
        int mp = idx >> 6, d = idx & 63;
        int m = mp >> 1, p = mp & 1;
        sa[idx] = g_attn[((size_t)(b * 16 + m) * NSV + (n * 2 + p)) * ND + d];
    }
    sc[tid]       = cw[tid];
    sc[tid + 256] = cw[tid + 256];
    __syncthreads();

    const int d  = tid & 63;
    const int h0 = tid >> 6;
#pragma unroll
    for (int r = 0; r < 4; r++) {
        int h = h0 + r * 4;
        float s = 0.f;
#pragma unroll
        for (int o = 0; o < 32; o++)
            s += sc[h * 32 + o] * sa[o * 64 + d];
        g_ctx[(size_t)bn * NHID + h * 64 + d] = s;
    }
}

// ---------------------------------------------------------------------------
extern "C" void kernel_launch(void* const* d_in, const int* in_sizes, int n_in,
                              void* d_out, int out_size)
{
    const float* x  = (const float*)d_in[0];
    const float* Wq = (const float*)d_in[1];
    const float* Wk = (const float*)d_in[2];
    const float* Wv = (const float*)d_in[3];
    const float* Wo = (const float*)d_in[4];
    const float* aq = (const float*)d_in[5];
    const float* ak = (const float*)d_in[6];
    const float* av = (const float*)d_in[7];
    const float* cw = (const float*)d_in[8];
    float* out = (float*)d_out;

    float *pProj, *pMix, *pAttn, *pCtx;
    cudaGetSymbolAddress((void**)&pProj, g_proj);
    cudaGetSymbolAddress((void**)&pMix,  g_mix);
    cudaGetSymbolAddress((void**)&pAttn, g_attn);
    cudaGetSymbolAddress((void**)&pCtx,  g_ctx);

    // 1) QKV projection (tensor cores, bf16x3 split precision)
    dim3 gProj(NHID / 128, NM / 128, 3);
    gemm3_mma<<<gProj, 256>>>(x, Wq, Wk, Wv,
                              pProj,
                              pProj + (size_t)NM * NHID,
                              pProj + 2 * (size_t)NM * NHID);

    // 2) head mixing
    mix_kernel<<<NM, 256>>>(aq, ak, av);

    // 3) causal flash attention (tensor cores, bf16x3)
    const int fSmem = (2 * 128 + 4 * 64) * FSTR * (int)sizeof(__nv_bfloat16); // 73728
    cudaFuncSetAttribute(flash_mma,
                         cudaFuncAttributeMaxDynamicSharedMemorySize, fSmem);
    dim3 gF(NSV / 128, NBH, 1);
    flash_mma<<<gF, 256, fSmem>>>(pMix,
                                  pMix + (size_t)NBH * NSV * ND,
                                  pMix + 2 * (size_t)NBH * NSV * ND,
                                  pAttn);

    // 4) collapse pseudo-heads
    collapse_kernel<<<NM, 256>>>(cw);

    // 5) output projection (tensor cores)
    dim3 gOut(NHID / 128, NM / 128, 1);
    gemm3_mma<<<gOut, 256>>>(pCtx, Wo, Wo, Wo, out, out, out);
}

// round 14
// speedup vs baseline: 2.1931x; 1.0144x over previous
#include <cuda_runtime.h>
#include <cuda_bf16.h>
#include <math.h>
#include <cstdint>

// Problem constants
#define NB   2
#define NS   1024
#define NHID 1024
#define NH   16
#define NP   2
#define ND   64
#define NBH  32          // NB*NH
#define NSV  2048        // NS*NP
#define NM   2048        // NB*NS
#define ATT_SCALE 0.125f // 1/sqrt(64)

// Scratch (no cudaMalloc allowed)
__device__ float g_proj[3][NM * NHID];            // q/k/v projections
__device__ float g_attn[NBH * NSV * ND];          // SDPA output
__device__ float g_ctx [NM * NHID];               // collapsed context
// pre-split bf16 planes for flash: [hi/lo][bh, vpos, d]
__device__ __nv_bfloat16 g_q16[2][NBH * NSV * ND];
__device__ __nv_bfloat16 g_k16[2][NBH * NSV * ND];
__device__ __nv_bfloat16 g_v16[2][NBH * NSV * ND];

// bf16 warp MMA: D = A(16x16,row) @ B(16x8,col) + D, fp32 accum.
__device__ __forceinline__ void mma16816(float* c, const uint32_t* a, const uint32_t* b) {
    asm volatile(
        "mma.sync.aligned.m16n8k16.row.col.f32.bf16.bf16.f32 "
        "{%0,%1,%2,%3}, {%4,%5,%6,%7}, {%8,%9}, {%0,%1,%2,%3};"
        : "+f"(c[0]), "+f"(c[1]), "+f"(c[2]), "+f"(c[3])
        : "r"(a[0]), "r"(a[1]), "r"(a[2]), "r"(a[3]), "r"(b[0]), "r"(b[1]));
}

__device__ __forceinline__ uint32_t pack_hi2(float x, float y) {
    __nv_bfloat162 t(__float2bfloat16(x), __float2bfloat16(y));
    return *reinterpret_cast<uint32_t*>(&t);
}
__device__ __forceinline__ uint32_t pack_lo2(float x, float y) {
    __nv_bfloat16 hx = __float2bfloat16(x), hy = __float2bfloat16(y);
    __nv_bfloat162 t(__float2bfloat16(x - __bfloat162float(hx)),
                     __float2bfloat16(y - __bfloat162float(hy)));
    return *reinterpret_cast<uint32_t*>(&t);
}

// ---------------------------------------------------------------------------
// bf16x3 split-precision tensor-core GEMM (unchanged from R9 WIN).
// ---------------------------------------------------------------------------
#define BK      32
#define ASTR    40

__global__ __launch_bounds__(256, 2)
void gemm3_mma(const float* __restrict__ A,
               const float* __restrict__ B0, const float* __restrict__ B1,
               const float* __restrict__ B2,
               float* __restrict__ C0, float* __restrict__ C1, float* __restrict__ C2)
{
    const float* Bw = (blockIdx.z == 0) ? B0 : (blockIdx.z == 1) ? B1 : B2;
    float*       C  = (blockIdx.z == 0) ? C0 : (blockIdx.z == 1) ? C1 : C2;

    __shared__ __align__(16) __nv_bfloat16 sAh[128 * ASTR];
    __shared__ __align__(16) __nv_bfloat16 sAl[128 * ASTR];
    __shared__ __align__(16) __nv_bfloat16 sBh[128 * ASTR];
    __shared__ __align__(16) __nv_bfloat16 sBl[128 * ASTR];

    const int tid  = threadIdx.x;
    const int wid  = tid >> 5;
    const int lane = tid & 31;
    const int wm   = wid & 3;
    const int wn   = wid >> 2;
    const int row0 = blockIdx.y * 128;
    const int col0 = blockIdx.x * 128;

    const int fr = lane >> 2;
    const int cp = lane & 3;

    float acc[2][8][4];
#pragma unroll
    for (int mi = 0; mi < 2; mi++)
#pragma unroll
        for (int ni = 0; ni < 8; ni++)
#pragma unroll
            for (int j = 0; j < 4; j++) acc[mi][ni][j] = 0.f;

    for (int kb = 0; kb < NHID; kb += BK) {
        __syncthreads();
#pragma unroll
        for (int i = 0; i < 4; i++) {
            int idx = tid + i * 256;
            int row = idx >> 3;
            int jc  = (idx & 7) * 4;

            float4 va = *(const float4*)&A[(size_t)(row0 + row) * NHID + kb + jc];
            *(uint2*)&sAh[row * ASTR + jc] =
                make_uint2(pack_hi2(va.x, va.y), pack_hi2(va.z, va.w));
            *(uint2*)&sAl[row * ASTR + jc] =
                make_uint2(pack_lo2(va.x, va.y), pack_lo2(va.z, va.w));

            float4 vb = *(const float4*)&Bw[(size_t)(col0 + row) * NHID + kb + jc];
            *(uint2*)&sBh[row * ASTR + jc] =
                make_uint2(pack_hi2(vb.x, vb.y), pack_hi2(vb.z, vb.w));
            *(uint2*)&sBl[row * ASTR + jc] =
                make_uint2(pack_lo2(vb.x, vb.y), pack_lo2(vb.z, vb.w));
        }
        __syncthreads();

#pragma unroll
        for (int ks = 0; ks < 2; ks++) {
            const int k0 = ks * 16;
            uint32_t ah[2][4], al[2][4];
#pragma unroll
            for (int mi = 0; mi < 2; mi++) {
                int rb = wm * 32 + mi * 16;
                const __nv_bfloat16* p0 = &sAh[(rb + fr) * ASTR + k0 + cp * 2];
                const __nv_bfloat16* p1 = &sAh[(rb + fr + 8) * ASTR + k0 + cp * 2];
                ah[mi][0] = *(const uint32_t*)p0;
                ah[mi][1] = *(const uint32_t*)p1;
                ah[mi][2] = *(const uint32_t*)(p0 + 8);
                ah[mi][3] = *(const uint32_t*)(p1 + 8);
                const __nv_bfloat16* q0 = &sAl[(rb + fr) * ASTR + k0 + cp * 2];
                const __nv_bfloat16* q1 = &sAl[(rb + fr + 8) * ASTR + k0 + cp * 2];
                al[mi][0] = *(const uint32_t*)q0;
                al[mi][1] = *(const uint32_t*)q1;
                al[mi][2] = *(const uint32_t*)(q0 + 8);
                al[mi][3] = *(const uint32_t*)(q1 + 8);
            }
#pragma unroll
            for (int ni = 0; ni < 8; ni++) {
                int nb = wn * 64 + ni * 8;
                const __nv_bfloat16* pb = &sBh[(nb + fr) * ASTR + k0 + cp * 2];
                const __nv_bfloat16* ql = &sBl[(nb + fr) * ASTR + k0 + cp * 2];
                uint32_t bh[2] = { *(const uint32_t*)pb, *(const uint32_t*)(pb + 8) };
                uint32_t bl[2] = { *(const uint32_t*)ql, *(const uint32_t*)(ql + 8) };
#pragma unroll
                for (int mi = 0; mi < 2; mi++) {
                    mma16816(acc[mi][ni], ah[mi], bh);
                    mma16816(acc[mi][ni], ah[mi], bl);
                    mma16816(acc[mi][ni], al[mi], bh);
                }
            }
        }
    }

#pragma unroll
    for (int mi = 0; mi < 2; mi++) {
#pragma unroll
        for (int ni = 0; ni < 8; ni++) {
            int row = row0 + wm * 32 + mi * 16 + fr;
            int col = col0 + wn * 64 + ni * 8 + cp * 2;
            *(float2*)&C[(size_t)row * NHID + col] =
                make_float2(acc[mi][ni][0], acc[mi][ni][1]);
            *(float2*)&C[(size_t)(row + 8) * NHID + col] =
                make_float2(acc[mi][ni][2], acc[mi][ni][3]);
        }
    }
}

// ---------------------------------------------------------------------------
// Head mixing + bf16 hi/lo pre-split (flash consumes the bf16 planes).
// ---------------------------------------------------------------------------
__global__ __launch_bounds__(256)
void mix_kernel(const float* __restrict__ aq, const float* __restrict__ ak,
                const float* __restrict__ av)
{
    __shared__ float srow[3][1024];
    __shared__ float sal[3][512];

    const int tid = threadIdx.x;
    const int bn  = blockIdx.x;
    const int b   = bn >> 10;
    const int n   = bn & 1023;

#pragma unroll
    for (int t = 0; t < 3; t++)
#pragma unroll
        for (int r = 0; r < 4; r++)
            srow[t][tid + r * 256] = g_proj[t][(size_t)bn * NHID + tid + r * 256];

    const float* al[3] = { aq, ak, av };
#pragma unroll
    for (int t = 0; t < 3; t++) {
        sal[t][tid]       = al[t][tid];
        sal[t][tid + 256] = al[t][tid + 256];
    }
    __syncthreads();

    const int d   = tid & 63;
    const int hp0 = tid >> 6;

#pragma unroll
    for (int t = 0; t < 3; t++) {
#pragma unroll
        for (int r = 0; r < 8; r++) {
            int hp = hp0 + r * 4;
            int h = hp >> 1, p = hp & 1;
            float s = 0.f;
#pragma unroll
            for (int m = 0; m < 16; m++)
                s += sal[t][(m * 16 + h) * 2 + p] * srow[t][m * 64 + d];
            size_t gi = ((size_t)(b * 16 + h) * NSV + (n * 2 + p)) * ND + d;
            __nv_bfloat16 hi = __float2bfloat16(s);
            __nv_bfloat16 lo = __float2bfloat16(s - __bfloat162float(hi));
            if (t == 0)      { g_q16[0][gi] = hi; g_q16[1][gi] = lo; }
            else if (t == 1) { g_k16[0][gi] = hi; g_k16[1][gi] = lo; }
            else             { g_v16[0][gi] = hi; g_v16[1][gi] = lo; }
        }
    }
}

// ---------------------------------------------------------------------------
// Flash attention, bf16x3 tensor cores. v2: pre-split inputs (no cvt in loop),
// register prefetch of next K/V tile overlapped with the MMA block.
// BQ=128 (8 warps x m16), BK=64; smem stride 72; V transposed w/ XOR swizzle.
// ---------------------------------------------------------------------------
#define FSTR 72

__global__ __launch_bounds__(256, 1)
void flash_mma(const __nv_bfloat16* __restrict__ Gqh, const __nv_bfloat16* __restrict__ Gql,
               const __nv_bfloat16* __restrict__ Gkh, const __nv_bfloat16* __restrict__ Gkl,
               const __nv_bfloat16* __restrict__ Gvh, const __nv_bfloat16* __restrict__ Gvl,
               float* __restrict__ O)
{
    extern __shared__ __nv_bfloat16 fsm[];
    __nv_bfloat16* Qh = fsm;                    // [128][72]
    __nv_bfloat16* Ql = Qh + 128 * FSTR;
    __nv_bfloat16* Kh = Ql + 128 * FSTR;        // [64][72] (row=kpos, col=d)
    __nv_bfloat16* Kl = Kh + 64 * FSTR;
    __nv_bfloat16* Vh = Kl + 64 * FSTR;         // [64][72] (row=d, col=kpos^swz)
    __nv_bfloat16* Vl = Vh + 64 * FSTR;

    const int tid  = threadIdx.x;
    const int wid  = tid >> 5;
    const int lane = tid & 31;
    const int fr   = lane >> 2;
    const int cp   = lane & 3;
    const int qt   = 15 - blockIdx.x;           // heavy tiles first
    const int bh   = blockIdx.y;

    // Q tile copy (bf16 planes, no conversion)
    {
        const __nv_bfloat16* qh = Gqh + ((size_t)bh * NSV + qt * 128) * ND;
        const __nv_bfloat16* ql = Gql + ((size_t)bh * NSV + qt * 128) * ND;
#pragma unroll
        for (int i = 0; i < 4; i++) {
            int idx = tid + i * 256;            // 0..1023 uint4 slots
            int row = idx >> 3;
            int jc  = (idx & 7) * 8;
            *(uint4*)&Qh[row * FSTR + jc] = *(const uint4*)&qh[row * ND + jc];
            *(uint4*)&Ql[row * FSTR + jc] = *(const uint4*)&ql[row * ND + jc];
        }
    }

    float m0 = -1e30f, m1 = -1e30f, l0 = 0.f, l1 = 0.f;
    float o[8][4];
#pragma unroll
    for (int nf = 0; nf < 8; nf++)
#pragma unroll
        for (int j = 0; j < 4; j++) o[nf][j] = 0.f;

    const int rowg0 = qt * 128 + wid * 16 + fr;
    const int rowg1 = rowg0 + 8;
    const int kts = 2 * qt + 2;

    // register prefetch buffers for next K/V tile
    uint4 rkh[2], rkl[2], rvh[2], rvl[2];
    auto prefetch = [&](int kt) {
        const __nv_bfloat16* kh = Gkh + ((size_t)bh * NSV + kt * 64) * ND;
        const __nv_bfloat16* kl = Gkl + ((size_t)bh * NSV + kt * 64) * ND;
        const __nv_bfloat16* vh = Gvh + ((size_t)bh * NSV + kt * 64) * ND;
        const __nv_bfloat16* vl = Gvl + ((size_t)bh * NSV + kt * 64) * ND;
#pragma unroll
        for (int i = 0; i < 2; i++) {
            int idx = tid + i * 256;            // 0..511 uint4 slots
            int off = (idx >> 3) * ND + (idx & 7) * 8;
            rkh[i] = *(const uint4*)&kh[off];
            rkl[i] = *(const uint4*)&kl[off];
            rvh[i] = *(const uint4*)&vh[off];
            rvl[i] = *(const uint4*)&vl[off];
        }
    };
    prefetch(0);

    for (int kt = 0; kt < kts; kt++) {
        __syncthreads();   // prior iter's fragment reads done (covers Q fill)
        // commit prefetched tile to smem
#pragma unroll
        for (int i = 0; i < 2; i++) {
            int idx = tid + i * 256;
            int row = idx >> 3;                 // kpos
            int jc  = (idx & 7) * 8;            // d base
            *(uint4*)&Kh[row * FSTR + jc] = rkh[i];
            *(uint4*)&Kl[row * FSTR + jc] = rkl[i];
            const __nv_bfloat16* ph = (const __nv_bfloat16*)&rvh[i];
            const __nv_bfloat16* pl = (const __nv_bfloat16*)&rvl[i];
#pragma unroll
            for (int e = 0; e < 8; e++) {
                int d  = jc + e;
                int kx = row ^ (((d >> 2) & 7) << 3);
                Vh[d * FSTR + kx] = ph[e];
                Vl[d * FSTR + kx] = pl[e];
            }
        }
        __syncthreads();
        if (kt + 1 < kts) prefetch(kt + 1);     // overlaps with MMA below

        // ---- S = Q @ K^T ----
        float s[8][4];
#pragma unroll
        for (int nf = 0; nf < 8; nf++)
#pragma unroll
            for (int j = 0; j < 4; j++) s[nf][j] = 0.f;

#pragma unroll
        for (int ds = 0; ds < 4; ds++) {
            const int k0 = ds * 16;
            const int rb = wid * 16;
            const __nv_bfloat16* p0 = &Qh[(rb + fr) * FSTR + k0 + cp * 2];
            const __nv_bfloat16* p1 = &Qh[(rb + fr + 8) * FSTR + k0 + cp * 2];
            uint32_t ah[4] = { *(const uint32_t*)p0, *(const uint32_t*)p1,
                               *(const uint32_t*)(p0 + 8), *(const uint32_t*)(p1 + 8) };
            const __nv_bfloat16* q0 = &Ql[(rb + fr) * FSTR + k0 + cp * 2];
            const __nv_bfloat16* q1 = &Ql[(rb + fr + 8) * FSTR + k0 + cp * 2];
            uint32_t al[4] = { *(const uint32_t*)q0, *(const uint32_t*)q1,
                               *(const uint32_t*)(q0 + 8), *(const uint32_t*)(q1 + 8) };
#pragma unroll
            for (int nf = 0; nf < 8; nf++) {
                int nb = nf * 8;
                const __nv_bfloat16* pb = &Kh[(nb + fr) * FSTR + k0 + cp * 2];
                const __nv_bfloat16* ql = &Kl[(nb + fr) * FSTR + k0 + cp * 2];
                uint32_t bh[2] = { *(const uint32_t*)pb, *(const uint32_t*)(pb + 8) };
                uint32_t bl[2] = { *(const uint32_t*)ql, *(const uint32_t*)(ql + 8) };
                mma16816(s[nf], ah, bh);
                mma16816(s[nf], ah, bl);
                mma16816(s[nf], al, bh);
            }
        }

        // ---- scale + causal mask ----
#pragma unroll
        for (int nf = 0; nf < 8; nf++) {
            int c0 = kt * 64 + nf * 8 + cp * 2;
            s[nf][0] = (c0     <= rowg0) ? s[nf][0] * ATT_SCALE : -1e30f;
            s[nf][1] = (c0 + 1 <= rowg0) ? s[nf][1] * ATT_SCALE : -1e30f;
            s[nf][2] = (c0     <= rowg1) ? s[nf][2] * ATT_SCALE : -1e30f;
            s[nf][3] = (c0 + 1 <= rowg1) ? s[nf][3] * ATT_SCALE : -1e30f;
        }

        // ---- online softmax ----
        float mx0 = -1e30f, mx1 = -1e30f;
#pragma unroll
        for (int nf = 0; nf < 8; nf++) {
            mx0 = fmaxf(mx0, fmaxf(s[nf][0], s[nf][1]));
            mx1 = fmaxf(mx1, fmaxf(s[nf][2], s[nf][3]));
        }
#pragma unroll
        for (int off = 1; off < 4; off <<= 1) {
            mx0 = fmaxf(mx0, __shfl_xor_sync(0xffffffffu, mx0, off));
            mx1 = fmaxf(mx1, __shfl_xor_sync(0xffffffffu, mx1, off));
        }
        float mn0 = fmaxf(m0, mx0), mn1 = fmaxf(m1, mx1);
        float cr0 = __expf(m0 - mn0), cr1 = __expf(m1 - mn1);
        float sm0 = 0.f, sm1 = 0.f;
#pragma unroll
        for (int nf = 0; nf < 8; nf++) {
            s[nf][0] = __expf(s[nf][0] - mn0);
            s[nf][1] = __expf(s[nf][1] - mn0);
            s[nf][2] = __expf(s[nf][2] - mn1);
            s[nf][3] = __expf(s[nf][3] - mn1);
            sm0 += s[nf][0] + s[nf][1];
            sm1 += s[nf][2] + s[nf][3];
        }
#pragma unroll
        for (int off = 1; off < 4; off <<= 1) {
            sm0 += __shfl_xor_sync(0xffffffffu, sm0, off);
            sm1 += __shfl_xor_sync(0xffffffffu, sm1, off);
        }
        l0 = l0 * cr0 + sm0;  m0 = mn0;
        l1 = l1 * cr1 + sm1;  m1 = mn1;
#pragma unroll
        for (int nf = 0; nf < 8; nf++) {
            o[nf][0] *= cr0; o[nf][1] *= cr0;
            o[nf][2] *= cr1; o[nf][3] *= cr1;
        }

        // ---- O += P @ V ----
#pragma unroll
        for (int ks = 0; ks < 4; ks++) {
            const int k0 = ks * 16;
            uint32_t ph[4], pl[4];
            ph[0] = pack_hi2(s[2*ks][0],   s[2*ks][1]);
            ph[1] = pack_hi2(s[2*ks][2],   s[2*ks][3]);
            ph[2] = pack_hi2(s[2*ks+1][0], s[2*ks+1][1]);
            ph[3] = pack_hi2(s[2*ks+1][2], s[2*ks+1][3]);
            pl[0] = pack_lo2(s[2*ks][0],   s[2*ks][1]);
            pl[1] = pack_lo2(s[2*ks][2],   s[2*ks][3]);
            pl[2] = pack_lo2(s[2*ks+1][0], s[2*ks+1][1]);
            pl[3] = pack_lo2(s[2*ks+1][2], s[2*ks+1][3]);
#pragma unroll
            for (int nf = 0; nf < 8; nf++) {
                int d  = nf * 8 + fr;
                int sw = ((d >> 2) & 7) << 3;
                int kx0 = (k0 + cp * 2) ^ sw;
                int kx1 = (k0 + cp * 2 + 8) ^ sw;
                uint32_t bh[2] = { *(const uint32_t*)&Vh[d * FSTR + kx0],
                                   *(const uint32_t*)&Vh[d * FSTR + kx1] };
                uint32_t bl[2] = { *(const uint32_t*)&Vl[d * FSTR + kx0],
                                   *(const uint32_t*)&Vl[d * FSTR + kx1] };
                mma16816(o[nf], ph, bh);
                mma16816(o[nf], ph, bl);
                mma16816(o[nf], pl, bh);
            }
        }
    }

    // ---- normalize + store ----
    float i0 = 1.0f / l0, i1 = 1.0f / l1;
    float* Op = O + ((size_t)bh * NSV) * ND;
#pragma unroll
    for (int nf = 0; nf < 8; nf++) {
        int col = nf * 8 + cp * 2;
        *(float2*)&Op[(size_t)rowg0 * ND + col] = make_float2(o[nf][0] * i0, o[nf][1] * i0);
        *(float2*)&Op[(size_t)rowg1 * ND + col] = make_float2(o[nf][2] * i1, o[nf][3] * i1);
    }
}

// ---------------------------------------------------------------------------
// Collapse pseudo-heads (unchanged)
// ---------------------------------------------------------------------------
__global__ __launch_bounds__(256)
void collapse_kernel(const float* __restrict__ cw)
{
    __shared__ float sa[2048];
    __shared__ float sc[512];

    const int tid = threadIdx.x;
    const int bn  = blockIdx.x;
    const int b   = bn >> 10;
    const int n   = bn & 1023;

#pragma unroll
    for (int r = 0; r < 8; r++) {
        int idx = tid + r * 256;
        int mp = idx >> 6, d = idx & 63;
        int m = mp >> 1, p = mp & 1;
        sa[idx] = g_attn[((size_t)(b * 16 + m) * NSV + (n * 2 + p)) * ND + d];
    }
    sc[tid]       = cw[tid];
    sc[tid + 256] = cw[tid + 256];
    __syncthreads();

    const int d  = tid & 63;
    const int h0 = tid >> 6;
#pragma unroll
    for (int r = 0; r < 4; r++) {
        int h = h0 + r * 4;
        float s = 0.f;
#pragma unroll
        for (int o = 0; o < 32; o++)
            s += sc[h * 32 + o] * sa[o * 64 + d];
        g_ctx[(size_t)bn * NHID + h * 64 + d] = s;
    }
}

// ---------------------------------------------------------------------------
extern "C" void kernel_launch(void* const* d_in, const int* in_sizes, int n_in,
                              void* d_out, int out_size)
{
    const float* x  = (const float*)d_in[0];
    const float* Wq = (const float*)d_in[1];
    const float* Wk = (const float*)d_in[2];
    const float* Wv = (const float*)d_in[3];
    const float* Wo = (const float*)d_in[4];
    const float* aq = (const float*)d_in[5];
    const float* ak = (const float*)d_in[6];
    const float* av = (const float*)d_in[7];
    const float* cw = (const float*)d_in[8];
    float* out = (float*)d_out;

    float *pProj, *pAttn, *pCtx;
    __nv_bfloat16 *pQ16, *pK16, *pV16;
    cudaGetSymbolAddress((void**)&pProj, g_proj);
    cudaGetSymbolAddress((void**)&pAttn, g_attn);
    cudaGetSymbolAddress((void**)&pCtx,  g_ctx);
    cudaGetSymbolAddress((void**)&pQ16,  g_q16);
    cudaGetSymbolAddress((void**)&pK16,  g_k16);
    cudaGetSymbolAddress((void**)&pV16,  g_v16);
    const size_t PLANE = (size_t)NBH * NSV * ND;

    // 1) QKV projection (tensor cores, bf16x3)
    dim3 gProj(NHID / 128, NM / 128, 3);
    gemm3_mma<<<gProj, 256>>>(x, Wq, Wk, Wv,
                              pProj,
                              pProj + (size_t)NM * NHID,
                              pProj + 2 * (size_t)NM * NHID);

    // 2) head mixing + bf16 hi/lo pre-split
    mix_kernel<<<NM, 256>>>(aq, ak, av);

    // 3) causal flash attention (tensor cores, bf16x3, prefetch pipeline)
    const int fSmem = (2 * 128 + 4 * 64) * FSTR * (int)sizeof(__nv_bfloat16); // 73728
    cudaFuncSetAttribute(flash_mma,
                         cudaFuncAttributeMaxDynamicSharedMemorySize, fSmem);
    dim3 gF(NSV / 128, NBH, 1);
    flash_mma<<<gF, 256, fSmem>>>(pQ16, pQ16 + PLANE,
                                  pK16, pK16 + PLANE,
                                  pV16, pV16 + PLANE,
                                  pAttn);

    // 4) collapse pseudo-heads
    collapse_kernel<<<NM, 256>>>(cw);

    // 5) output projection (tensor cores)
    dim3 gOut(NHID / 128, NM / 128, 1);
    gemm3_mma<<<gOut, 256>>>(pCtx, Wo, Wo, Wo, out, out, out);
}